// round 7
// baseline (speedup 1.0000x reference)
#include <cuda_runtime.h>
#include <cuda_bf16.h>
#include <cstdint>
#include <cstddef>

#define BATCH 32
#define SEQ   512
#define ISZ   512
#define HSZ   1024
#define G4    4096
#define NB2   128
#define NT2   256

typedef unsigned long long ull;

// ---------------------------------------------------------------------------
// Device scratch (allocation-free rule: __device__ globals).
// g_Xg: [s][b][4096] input projections + bias, fp32, 256MB.
// g_hT: ping-pong hidden state, transposed h_T[k][b] so reads coalesce.
// ---------------------------------------------------------------------------
__device__ float    g_Xg[(size_t)SEQ * BATCH * G4];
__device__ float    g_hT[2][HSZ * BATCH];
__device__ unsigned g_cnt;

// ---------------------------------------------------------------------------
// f32x2 packed fp32 FMA (sm_100+): 2 MACs/instr.
// ---------------------------------------------------------------------------
__device__ __forceinline__ void fma2(ull& d, ull a, ull b) {
    asm("fma.rn.f32x2 %0, %1, %2, %0;" : "+l"(d) : "l"(a), "l"(b));
}
__device__ __forceinline__ ull pk2(float x, float y) {
    ull r; asm("mov.b64 %0, {%1, %2};" : "=l"(r) : "f"(x), "f"(y)); return r;
}
__device__ __forceinline__ float2 upk(ull v) {
    float2 r; asm("mov.b64 {%0, %1}, %2;" : "=f"(r.x), "=f"(r.y) : "l"(v)); return r;
}

// ---------------------------------------------------------------------------
// Init: zero h0 and barrier counter (must run every launch — graph replays).
// ---------------------------------------------------------------------------
__global__ void lstm_init() {
    unsigned t = blockIdx.x * blockDim.x + threadIdx.x;
    if (t == 0) g_cnt = 0u;
    unsigned stride = gridDim.x * blockDim.x;
    for (unsigned i = t; i < HSZ * BATCH; i += stride) {
        g_hT[0][i] = 0.f;
        g_hT[1][i] = 0.f;
    }
}

// ---------------------------------------------------------------------------
// Phase 1: Xg[m][g] = X_row(m) . W[:,g] + bias[g],  m = s*32 + b.
// M=16384, N=4096, K=512. 128x128 tile, BK=16, 256 threads, 8x8/thread, f32x2.
// As staged duplicated {a,a} so the inner loop needs no pack instructions.
// ---------------------------------------------------------------------------
__global__ __launch_bounds__(256, 2)
void xg_gemm(const float* __restrict__ X,
             const float* __restrict__ w0, const float* __restrict__ w1,
             const float* __restrict__ w2, const float* __restrict__ w3,
             const float* __restrict__ bi0, const float* __restrict__ bi1,
             const float* __restrict__ bi2, const float* __restrict__ bi3)
{
    __shared__ float2 As2[16 * 128];   // [k][m] duplicated pairs, 16KB
    __shared__ float  Bs [16 * 128];   // [k][n], 8KB

    const int tid  = threadIdx.x;
    const int n0   = blockIdx.x * 128;
    const int m0   = blockIdx.y * 128;
    const int gate = blockIdx.x >> 3;          // 128-col tiles, 8 per gate
    const float* W  = (gate == 0) ? w0 : (gate == 1) ? w1 : (gate == 2) ? w2 : w3;
    const float* Bv = (gate == 0) ? bi0 : (gate == 1) ? bi1 : (gate == 2) ? bi2 : bi3;
    const int nloc = n0 & 1023;

    // A-load mapping: row = tid&127 (consecutive tids -> consecutive rows, so
    // STS to As2 is conflict-free), two float4 k-slots per thread.
    const int ar  = tid & 127;
    const int as4 = tid >> 7;                  // 0..1
    const int mg  = m0 + ar;                   // global m = s*32+b
    const float* Xrow = X + ((size_t)(mg & 31) * SEQ + (size_t)(mg >> 5)) * ISZ;

    // B-load mapping: coalesced float4 along n.
    const int bn4 = (tid & 31) * 4;
    const int bkr = tid >> 5;                  // 0..7

    const int tx = tid & 15, ty = tid >> 4;

    ull acc[8][4];
    #pragma unroll
    for (int i = 0; i < 8; ++i)
        #pragma unroll
        for (int j = 0; j < 4; ++j) acc[i][j] = 0ULL;

    for (int kt = 0; kt < ISZ; kt += 16) {
        float4 a0 = *(const float4*)(Xrow + kt + as4 * 4);
        float4 a1 = *(const float4*)(Xrow + kt + (as4 + 2) * 4);
        float4 b0 = *(const float4*)(W + (size_t)(kt + bkr)     * HSZ + nloc + bn4);
        float4 b1 = *(const float4*)(W + (size_t)(kt + bkr + 8) * HSZ + nloc + bn4);

        __syncthreads();   // protect previous tile's smem reads
        As2[(as4 * 4 + 0) * 128 + ar] = make_float2(a0.x, a0.x);
        As2[(as4 * 4 + 1) * 128 + ar] = make_float2(a0.y, a0.y);
        As2[(as4 * 4 + 2) * 128 + ar] = make_float2(a0.z, a0.z);
        As2[(as4 * 4 + 3) * 128 + ar] = make_float2(a0.w, a0.w);
        As2[((as4 + 2) * 4 + 0) * 128 + ar] = make_float2(a1.x, a1.x);
        As2[((as4 + 2) * 4 + 1) * 128 + ar] = make_float2(a1.y, a1.y);
        As2[((as4 + 2) * 4 + 2) * 128 + ar] = make_float2(a1.z, a1.z);
        As2[((as4 + 2) * 4 + 3) * 128 + ar] = make_float2(a1.w, a1.w);
        *(float4*)(Bs + bkr * 128 + bn4)       = b0;
        *(float4*)(Bs + (bkr + 8) * 128 + bn4) = b1;
        __syncthreads();

        #pragma unroll
        for (int k = 0; k < 16; ++k) {
            ull a[8], bb[4];
            ulonglong2 p;
            p = *(const ulonglong2*)(As2 + k * 128 + ty * 8);     a[0] = p.x; a[1] = p.y;
            p = *(const ulonglong2*)(As2 + k * 128 + ty * 8 + 2); a[2] = p.x; a[3] = p.y;
            p = *(const ulonglong2*)(As2 + k * 128 + ty * 8 + 4); a[4] = p.x; a[5] = p.y;
            p = *(const ulonglong2*)(As2 + k * 128 + ty * 8 + 6); a[6] = p.x; a[7] = p.y;
            p = *(const ulonglong2*)(Bs + k * 128 + tx * 8);      bb[0] = p.x; bb[1] = p.y;
            p = *(const ulonglong2*)(Bs + k * 128 + tx * 8 + 4);  bb[2] = p.x; bb[3] = p.y;
            #pragma unroll
            for (int i = 0; i < 8; ++i)
                #pragma unroll
                for (int j = 0; j < 4; ++j) fma2(acc[i][j], a[i], bb[j]);
        }
    }

    // Epilogue: unpack, add bias, store to g_Xg.
    float4 bb0 = *(const float4*)(Bv + nloc + tx * 8);
    float4 bb1 = *(const float4*)(Bv + nloc + tx * 8 + 4);
    #pragma unroll
    for (int i = 0; i < 8; ++i) {
        float2 c0 = upk(acc[i][0]), c1 = upk(acc[i][1]);
        float2 c2 = upk(acc[i][2]), c3 = upk(acc[i][3]);
        float4 o0 = make_float4(c0.x + bb0.x, c0.y + bb0.y, c1.x + bb0.z, c1.y + bb0.w);
        float4 o1 = make_float4(c2.x + bb1.x, c2.y + bb1.y, c3.x + bb1.z, c3.y + bb1.w);
        size_t row = (size_t)(m0 + ty * 8 + i) * G4 + n0 + tx * 8;
        *(float4*)(g_Xg + row)     = o0;
        *(float4*)(g_Xg + row + 4) = o1;
    }
}

// ---------------------------------------------------------------------------
// Phase 2: persistent recurrence. 128 blocks x 256 threads, all co-resident.
// Block hb owns hidden units hb*8..hb*8+7 for all 4 gates and all 32 batches
// (1024 outputs, K=1024). Split-K=4 inside the block: thread = (og, ks),
// og in [0,64): 4 batches x 4 gate-cols microtile; ks in [0,4): k-range 256.
// h_T staged to smem per step (LDS.128 of 4 batches); u read via LDG.128
// from L2-resident U (16MB). One atomic grid barrier per step (h ping-pong).
// smem: Hs 128KB + Rs 16KB + Gs 4KB = 148KB -> 1 block/SM.
// ---------------------------------------------------------------------------
#define SMEM_P2 ((32768 + 4096 + 1024) * 4)

__global__ __launch_bounds__(NT2, 1)
void lstm_rec(const float* __restrict__ u0, const float* __restrict__ u1,
              const float* __restrict__ u2, const float* __restrict__ u3,
              float* __restrict__ out)
{
    extern __shared__ float sm[];
    float* Hs = sm;                      // [k][b], 1024*32 fp32
    float* Rs = sm + 32768;              // [ks][1024] split-K partials
    float* Gs = sm + 32768 + 4096;       // [b][32] gate pre-activations

    const int tid = threadIdx.x;
    const int hb  = blockIdx.x;                    // 0..127

    // compute role
    const int og   = tid & 63;
    const int ks   = tid >> 6;                     // 0..3
    const int bg   = og & 7;                       // batch group: b = bg*4..+3
    const int cgrp = og >> 3;                      // col group: c = cgrp*4..+3 (c in 0..31)
    const int gate = cgrp >> 1;                    // 4 contiguous cols, one gate
    const float* up4[4] = {u0, u1, u2, u3};
    const float* uptr = up4[gate] + hb * 8 + (cgrp & 1) * 4;
    const int kbeg = ks * 256;

    // epilogue role: (batch ub, hidden j) — fixed across steps, c in register
    const int ub = tid >> 3;
    const int j  = tid & 7;
    const int kglob = hb * 8 + j;
    float creg = 0.f;

    float* out_h = out + (size_t)BATCH * SEQ * HSZ;
    float* out_c = out_h + BATCH * HSZ;

    int cur = 0;
    for (int s = 0; s < SEQ; ++s) {
        // --- stage h_T for this step (L2 path; other SMs wrote it) ---
        const float* hsrc = g_hT[cur];
        #pragma unroll 4
        for (int q = 0; q < 32; ++q) {
            int f = q * 1024 + tid * 4;
            float4 v = __ldcg((const float4*)(hsrc + f));
            *(float4*)(Hs + f) = v;
        }
        __syncthreads();

        // --- split-K GEMM: acc[lb][p] pairs along cols ---
        ull acc00 = 0, acc01 = 0, acc10 = 0, acc11 = 0;
        ull acc20 = 0, acc21 = 0, acc30 = 0, acc31 = 0;
        const float* hk = Hs + bg * 4;
        #pragma unroll 8
        for (int k = kbeg; k < kbeg + 256; ++k) {
            float4 h4 = *(const float4*)(hk + k * 32);
            ulonglong2 uu = *(const ulonglong2*)(uptr + (size_t)k * HSZ);
            ull h0 = pk2(h4.x, h4.x);
            ull h1 = pk2(h4.y, h4.y);
            ull h2 = pk2(h4.z, h4.z);
            ull h3 = pk2(h4.w, h4.w);
            fma2(acc00, h0, uu.x); fma2(acc01, h0, uu.y);
            fma2(acc10, h1, uu.x); fma2(acc11, h1, uu.y);
            fma2(acc20, h2, uu.x); fma2(acc21, h2, uu.y);
            fma2(acc30, h3, uu.x); fma2(acc31, h3, uu.y);
        }

        // --- write split-K partials ---
        {
            float* r = Rs + ks * 1024 + og * 16;
            float2 t;
            t = upk(acc00); r[0]  = t.x; r[1]  = t.y;
            t = upk(acc01); r[2]  = t.x; r[3]  = t.y;
            t = upk(acc10); r[4]  = t.x; r[5]  = t.y;
            t = upk(acc11); r[6]  = t.x; r[7]  = t.y;
            t = upk(acc20); r[8]  = t.x; r[9]  = t.y;
            t = upk(acc21); r[10] = t.x; r[11] = t.y;
            t = upk(acc30); r[12] = t.x; r[13] = t.y;
            t = upk(acc31); r[14] = t.x; r[15] = t.y;
        }
        __syncthreads();

        // --- reduce 4 partials + add Xg -> Gs[b][c] ---
        #pragma unroll
        for (int i = 0; i < 4; ++i) {
            int o   = tid * 4 + i;
            int oog = o >> 4, li = o & 15;
            int bb  = (oog & 7) * 4 + (li >> 2);
            int cc  = (oog >> 3) * 4 + (li & 3);
            float v = Rs[o] + Rs[1024 + o] + Rs[2048 + o] + Rs[3072 + o];
            int gcol = (cc >> 3) * HSZ + hb * 8 + (cc & 7);
            v += g_Xg[((size_t)s * BATCH + bb) * G4 + gcol];
            Gs[bb * 32 + cc] = v;
        }
        __syncthreads();

        // --- gate nonlinearity + state update (role: ub, j) ---
        {
            float gi = Gs[ub * 32 + j];
            float gf = Gs[ub * 32 + 8 + j];
            float gc = Gs[ub * 32 + 16 + j];
            float go = Gs[ub * 32 + 24 + j];
            float it = 1.f / (1.f + __expf(-gi));
            float ft = 1.f / (1.f + __expf(-gf));
            float ct = tanhf(gc);
            float ot = 1.f / (1.f + __expf(-go));
            creg = ft * creg + it * ct;
            float hn = ot * tanhf(creg);
            __stcg(&g_hT[cur ^ 1][kglob * 32 + ub], hn);
            out[((size_t)ub * SEQ + s) * HSZ + kglob] = hn;
            if (s == SEQ - 1) {
                out_h[ub * HSZ + kglob] = hn;
                out_c[ub * HSZ + kglob] = creg;
            }
        }

        // --- grid barrier (release h writes, then arrive+spin) ---
        __threadfence();
        __syncthreads();
        if (tid == 0) {
            atomicAdd(&g_cnt, 1u);
            unsigned target = (unsigned)NB2 * (unsigned)(s + 1);
            while (*((volatile unsigned*)&g_cnt) < target) { }
            __threadfence();
        }
        __syncthreads();
        cur ^= 1;
    }
}

// ---------------------------------------------------------------------------
// Launch. Inputs (metadata order): X, w_i,u_i,b_i, w_f,u_f,b_f, w_c,u_c,b_c,
// w_o,u_o,b_o. Output: [hidden_seq (B,S,H) | h_T (B,H) | c_T (B,H)] fp32.
// ---------------------------------------------------------------------------
extern "C" void kernel_launch(void* const* d_in, const int* in_sizes, int n_in,
                              void* d_out, int out_size) {
    (void)in_sizes; (void)n_in; (void)out_size;
    const float* X   = (const float*)d_in[0];
    const float* w_i = (const float*)d_in[1];
    const float* u_i = (const float*)d_in[2];
    const float* b_i = (const float*)d_in[3];
    const float* w_f = (const float*)d_in[4];
    const float* u_f = (const float*)d_in[5];
    const float* b_f = (const float*)d_in[6];
    const float* w_c = (const float*)d_in[7];
    const float* u_c = (const float*)d_in[8];
    const float* b_c = (const float*)d_in[9];
    const float* w_o = (const float*)d_in[10];
    const float* u_o = (const float*)d_in[11];
    const float* b_o = (const float*)d_in[12];
    float* out = (float*)d_out;

    lstm_init<<<64, 256>>>();

    dim3 g1(32, 128);   // N/128 x M/128
    xg_gemm<<<g1, 256>>>(X, w_i, w_f, w_c, w_o, b_i, b_f, b_c, b_o);

    cudaFuncSetAttribute(lstm_rec, cudaFuncAttributeMaxDynamicSharedMemorySize,
                         SMEM_P2);
    lstm_rec<<<NB2, NT2, SMEM_P2>>>(u_i, u_f, u_c, u_o, out);
}

// round 8
// speedup vs baseline: 1.1214x; 1.1214x over previous
#include <cuda_runtime.h>
#include <cuda_bf16.h>
#include <cstdint>
#include <cstddef>

#define BATCH 32
#define SEQ   512
#define ISZ   512
#define HSZ   1024
#define G4    4096
#define NB2   128
#define NT2   256

typedef unsigned long long ull;

// ---------------------------------------------------------------------------
// Device scratch (allocation-free rule: __device__ globals).
// g_Xg: [s][b][4096] input projections + bias, fp32, 256MB.
// g_hT: ping-pong hidden state, transposed h_T[k][b] so reads coalesce.
// ---------------------------------------------------------------------------
__device__ float    g_Xg[(size_t)SEQ * BATCH * G4];
__device__ float    g_hT[2][HSZ * BATCH];
__device__ unsigned g_cnt;

// ---------------------------------------------------------------------------
// f32x2 packed fp32 FMA (sm_100+): 2 MACs/instr.
// ---------------------------------------------------------------------------
__device__ __forceinline__ void fma2(ull& d, ull a, ull b) {
    asm("fma.rn.f32x2 %0, %1, %2, %0;" : "+l"(d) : "l"(a), "l"(b));
}
__device__ __forceinline__ ull pk2(float x, float y) {
    ull r; asm("mov.b64 %0, {%1, %2};" : "=l"(r) : "f"(x), "f"(y)); return r;
}
__device__ __forceinline__ float2 upk(ull v) {
    float2 r; asm("mov.b64 {%0, %1}, %2;" : "=f"(r.x), "=f"(r.y) : "l"(v)); return r;
}

// cp.async 16B, L1-bypass (.cg) — reads L2 directly (coherent with stcg writes).
__device__ __forceinline__ void cpa16(uint32_t saddr, const void* gptr) {
    asm volatile("cp.async.cg.shared.global [%0], [%1], 16;"
                 :: "r"(saddr), "l"(gptr) : "memory");
}
__device__ __forceinline__ void cpa_wait_all() {
    asm volatile("cp.async.commit_group;\n\tcp.async.wait_group 0;" ::: "memory");
}

// ---------------------------------------------------------------------------
// Init: zero h0 and barrier counter (must run every launch — graph replays).
// ---------------------------------------------------------------------------
__global__ void lstm_init() {
    unsigned t = blockIdx.x * blockDim.x + threadIdx.x;
    if (t == 0) g_cnt = 0u;
    unsigned stride = gridDim.x * blockDim.x;
    for (unsigned i = t; i < HSZ * BATCH; i += stride) {
        g_hT[0][i] = 0.f;
        g_hT[1][i] = 0.f;
    }
}

// ---------------------------------------------------------------------------
// Phase 1: Xg[m][g] = X_row(m) . W[:,g] + bias[g],  m = s*32 + b.
// M=16384, N=4096, K=512. 128x128 tile, BK=16, 256 threads, 8x8/thread, f32x2.
// (Known-good from R5/R7; unchanged this round.)
// ---------------------------------------------------------------------------
__global__ __launch_bounds__(256, 2)
void xg_gemm(const float* __restrict__ X,
             const float* __restrict__ w0, const float* __restrict__ w1,
             const float* __restrict__ w2, const float* __restrict__ w3,
             const float* __restrict__ bi0, const float* __restrict__ bi1,
             const float* __restrict__ bi2, const float* __restrict__ bi3)
{
    __shared__ float2 As2[16 * 128];   // [k][m] duplicated pairs, 16KB
    __shared__ float  Bs [16 * 128];   // [k][n], 8KB

    const int tid  = threadIdx.x;
    const int n0   = blockIdx.x * 128;
    const int m0   = blockIdx.y * 128;
    const int gate = blockIdx.x >> 3;          // 128-col tiles, 8 per gate
    const float* W  = (gate == 0) ? w0 : (gate == 1) ? w1 : (gate == 2) ? w2 : w3;
    const float* Bv = (gate == 0) ? bi0 : (gate == 1) ? bi1 : (gate == 2) ? bi2 : bi3;
    const int nloc = n0 & 1023;

    const int ar  = tid & 127;
    const int as4 = tid >> 7;                  // 0..1
    const int mg  = m0 + ar;                   // global m = s*32+b
    const float* Xrow = X + ((size_t)(mg & 31) * SEQ + (size_t)(mg >> 5)) * ISZ;

    const int bn4 = (tid & 31) * 4;
    const int bkr = tid >> 5;                  // 0..7

    const int tx = tid & 15, ty = tid >> 4;

    ull acc[8][4];
    #pragma unroll
    for (int i = 0; i < 8; ++i)
        #pragma unroll
        for (int j = 0; j < 4; ++j) acc[i][j] = 0ULL;

    for (int kt = 0; kt < ISZ; kt += 16) {
        float4 a0 = *(const float4*)(Xrow + kt + as4 * 4);
        float4 a1 = *(const float4*)(Xrow + kt + (as4 + 2) * 4);
        float4 b0 = *(const float4*)(W + (size_t)(kt + bkr)     * HSZ + nloc + bn4);
        float4 b1 = *(const float4*)(W + (size_t)(kt + bkr + 8) * HSZ + nloc + bn4);

        __syncthreads();   // protect previous tile's smem reads
        As2[(as4 * 4 + 0) * 128 + ar] = make_float2(a0.x, a0.x);
        As2[(as4 * 4 + 1) * 128 + ar] = make_float2(a0.y, a0.y);
        As2[(as4 * 4 + 2) * 128 + ar] = make_float2(a0.z, a0.z);
        As2[(as4 * 4 + 3) * 128 + ar] = make_float2(a0.w, a0.w);
        As2[((as4 + 2) * 4 + 0) * 128 + ar] = make_float2(a1.x, a1.x);
        As2[((as4 + 2) * 4 + 1) * 128 + ar] = make_float2(a1.y, a1.y);
        As2[((as4 + 2) * 4 + 2) * 128 + ar] = make_float2(a1.z, a1.z);
        As2[((as4 + 2) * 4 + 3) * 128 + ar] = make_float2(a1.w, a1.w);
        *(float4*)(Bs + bkr * 128 + bn4)       = b0;
        *(float4*)(Bs + (bkr + 8) * 128 + bn4) = b1;
        __syncthreads();

        #pragma unroll
        for (int k = 0; k < 16; ++k) {
            ull a[8], bb[4];
            ulonglong2 p;
            p = *(const ulonglong2*)(As2 + k * 128 + ty * 8);     a[0] = p.x; a[1] = p.y;
            p = *(const ulonglong2*)(As2 + k * 128 + ty * 8 + 2); a[2] = p.x; a[3] = p.y;
            p = *(const ulonglong2*)(As2 + k * 128 + ty * 8 + 4); a[4] = p.x; a[5] = p.y;
            p = *(const ulonglong2*)(As2 + k * 128 + ty * 8 + 6); a[6] = p.x; a[7] = p.y;
            p = *(const ulonglong2*)(Bs + k * 128 + tx * 8);      bb[0] = p.x; bb[1] = p.y;
            p = *(const ulonglong2*)(Bs + k * 128 + tx * 8 + 4);  bb[2] = p.x; bb[3] = p.y;
            #pragma unroll
            for (int i = 0; i < 8; ++i)
                #pragma unroll
                for (int j = 0; j < 4; ++j) fma2(acc[i][j], a[i], bb[j]);
        }
    }

    float4 bb0 = *(const float4*)(Bv + nloc + tx * 8);
    float4 bb1 = *(const float4*)(Bv + nloc + tx * 8 + 4);
    #pragma unroll
    for (int i = 0; i < 8; ++i) {
        float2 c0 = upk(acc[i][0]), c1 = upk(acc[i][1]);
        float2 c2 = upk(acc[i][2]), c3 = upk(acc[i][3]);
        float4 o0 = make_float4(c0.x + bb0.x, c0.y + bb0.y, c1.x + bb0.z, c1.y + bb0.w);
        float4 o1 = make_float4(c2.x + bb1.x, c2.y + bb1.y, c3.x + bb1.z, c3.y + bb1.w);
        size_t row = (size_t)(m0 + ty * 8 + i) * G4 + n0 + tx * 8;
        *(float4*)(g_Xg + row)     = o0;
        *(float4*)(g_Xg + row + 4) = o1;
    }
}

// ---------------------------------------------------------------------------
// Phase 2: persistent recurrence. 128 blocks x 256 threads, all co-resident.
// Block hb owns hidden units hb*8..hb*8+7, all 4 gates, all 32 batches
// (1024 outputs, K=1024). Split-K=4: thread = (og, ks); og: 4 batches x 4
// gate-cols microtile; ks: k-range 256.
// R7 changes: (1) cp.async.cg staging of h + this step's Xg slice;
// (2) double-buffered register prefetch of U (groups of 8 k-iters), with
// next-step group-0 prefetched before the grid barrier;
// (3) reduce reads Xg from smem.
// smem: Hs 128KB + Rs 16KB + Gs 4KB + XgS 4KB = 152KB -> 1 block/SM.
// ---------------------------------------------------------------------------
#define SMEM_P2 ((32768 + 4096 + 1024 + 1024) * 4)

// compute one group of 8 k-iters with prefetched U buffer UB; G = absolute group
#define GRP(UB, G) do {                                                        \
    _Pragma("unroll")                                                          \
    for (int i_ = 0; i_ < 8; ++i_) {                                           \
        const float* hp_ = Hs + (size_t)((G) * 8 + i_) * 32 + bg * 4;          \
        float4 h4_ = *(const float4*)hp_;                                      \
        ull h0_ = pk2(h4_.x, h4_.x), h1_ = pk2(h4_.y, h4_.y);                  \
        ull h2_ = pk2(h4_.z, h4_.z), h3_ = pk2(h4_.w, h4_.w);                  \
        fma2(acc00, h0_, UB[i_].x); fma2(acc01, h0_, UB[i_].y);                \
        fma2(acc10, h1_, UB[i_].x); fma2(acc11, h1_, UB[i_].y);                \
        fma2(acc20, h2_, UB[i_].x); fma2(acc21, h2_, UB[i_].y);                \
        fma2(acc30, h3_, UB[i_].x); fma2(acc31, h3_, UB[i_].y);                \
    }                                                                          \
} while (0)

// prefetch group G (relative to this thread's kbeg) of U into register buffer
#define PF(UB, G) do {                                                         \
    _Pragma("unroll")                                                          \
    for (int i_ = 0; i_ < 8; ++i_)                                             \
        UB[i_] = *(const ulonglong2*)(ubase + (size_t)((G) * 8 + i_) * HSZ);   \
} while (0)

__global__ __launch_bounds__(NT2, 1)
void lstm_rec(const float* __restrict__ u0, const float* __restrict__ u1,
              const float* __restrict__ u2, const float* __restrict__ u3,
              float* __restrict__ out)
{
    extern __shared__ float sm[];
    float* Hs  = sm;                         // [k][b], 1024*32 fp32 (128KB)
    float* Rs  = sm + 32768;                 // [ks][1024] split-K partials
    float* Gs  = sm + 32768 + 4096;          // [b][32] gate pre-activations
    float* XgS = sm + 32768 + 4096 + 1024;   // [b][32] this step's Xg slice

    const int tid = threadIdx.x;
    const int hb  = blockIdx.x;                    // 0..127

    // compute role
    const int og   = tid & 63;
    const int ks   = tid >> 6;                     // 0..3
    const int bg   = og & 7;                       // batches bg*4..+3
    const int cgrp = og >> 3;                      // cols cgrp*4..+3 (of 32)
    const int gate = cgrp >> 1;
    const float* up4[4] = {u0, u1, u2, u3};
    const float* uptr  = up4[gate] + hb * 8 + (cgrp & 1) * 4;
    const int    kbeg  = ks * 256;
    const int    kb8   = ks * 32;                  // absolute group base
    const float* ubase = uptr + (size_t)kbeg * HSZ;

    // epilogue role: (batch ub, hidden j) — fixed across steps, c in register
    const int ub = tid >> 3;
    const int j  = tid & 7;
    const int kglob = hb * 8 + j;
    float creg = 0.f;

    // Xg staging role: 16B chunk per thread: batch xb, 4-col group xq
    const int xb = tid >> 3, xq = tid & 7;
    const size_t xgcol = (size_t)(xq >> 1) * 1024 + hb * 8 + (xq & 1) * 4;

    const uint32_t HsA  = (uint32_t)__cvta_generic_to_shared(Hs);
    const uint32_t XgA  = (uint32_t)__cvta_generic_to_shared(XgS);

    float* out_h = out + (size_t)BATCH * SEQ * HSZ;
    float* out_c = out_h + BATCH * HSZ;

    ulonglong2 ub0[8], ub1[8];
    PF(ub0, 0);                        // group 0 for step 0 (U is step-invariant)

    int cur = 0;
    for (int s = 0; s < SEQ; ++s) {
        // --- stage h_T + Xg slice via cp.async (L2 path, L1 bypass) ---
        const float* hsrc = g_hT[cur];
        #pragma unroll
        for (int q = 0; q < 32; ++q) {
            int f = q * 1024 + tid * 4;
            cpa16(HsA + (uint32_t)f * 4u, hsrc + f);
        }
        cpa16(XgA + (uint32_t)(xb * 32 + xq * 4) * 4u,
              g_Xg + ((size_t)s * BATCH + xb) * G4 + xgcol);
        cpa_wait_all();
        __syncthreads();

        // --- split-K GEMM with double-buffered U prefetch ---
        ull acc00 = 0, acc01 = 0, acc10 = 0, acc11 = 0;
        ull acc20 = 0, acc21 = 0, acc30 = 0, acc31 = 0;
        for (int g = 0; g < 32; g += 2) {
            PF(ub1, g + 1);
            GRP(ub0, kb8 + g);
            if (g < 30) PF(ub0, g + 2);
            else        PF(ub0, 0);            // next step's group 0
            GRP(ub1, kb8 + g + 1);
        }

        // --- write split-K partials ---
        {
            float* r = Rs + ks * 1024 + og * 16;
            float2 t;
            t = upk(acc00); r[0]  = t.x; r[1]  = t.y;
            t = upk(acc01); r[2]  = t.x; r[3]  = t.y;
            t = upk(acc10); r[4]  = t.x; r[5]  = t.y;
            t = upk(acc11); r[6]  = t.x; r[7]  = t.y;
            t = upk(acc20); r[8]  = t.x; r[9]  = t.y;
            t = upk(acc21); r[10] = t.x; r[11] = t.y;
            t = upk(acc30); r[12] = t.x; r[13] = t.y;
            t = upk(acc31); r[14] = t.x; r[15] = t.y;
        }
        __syncthreads();

        // --- reduce 4 partials + add Xg (smem) -> Gs[b][c] ---
        #pragma unroll
        for (int i = 0; i < 4; ++i) {
            int o   = tid * 4 + i;
            int oog = o >> 4, li = o & 15;
            int bb  = (oog & 7) * 4 + (li >> 2);
            int cc  = (oog >> 3) * 4 + (li & 3);
            float v = Rs[o] + Rs[1024 + o] + Rs[2048 + o] + Rs[3072 + o];
            v += XgS[bb * 32 + cc];
            Gs[bb * 32 + cc] = v;
        }
        __syncthreads();

        // --- gate nonlinearity + state update (role: ub, j) ---
        {
            float gi = Gs[ub * 32 + j];
            float gf = Gs[ub * 32 + 8 + j];
            float gc = Gs[ub * 32 + 16 + j];
            float go = Gs[ub * 32 + 24 + j];
            float it = 1.f / (1.f + __expf(-gi));
            float ft = 1.f / (1.f + __expf(-gf));
            float ct = tanhf(gc);
            float ot = 1.f / (1.f + __expf(-go));
            creg = ft * creg + it * ct;
            float hn = ot * tanhf(creg);
            __stcg(&g_hT[cur ^ 1][kglob * 32 + ub], hn);
            out[((size_t)ub * SEQ + s) * HSZ + kglob] = hn;
            if (s == SEQ - 1) {
                out_h[ub * HSZ + kglob] = hn;
                out_c[ub * HSZ + kglob] = creg;
            }
        }

        // --- grid barrier (release h writes, then arrive+spin) ---
        __threadfence();
        __syncthreads();
        if (tid == 0) {
            atomicAdd(&g_cnt, 1u);
            unsigned target = (unsigned)NB2 * (unsigned)(s + 1);
            while (*((volatile unsigned*)&g_cnt) < target) { }
            __threadfence();
        }
        __syncthreads();
        cur ^= 1;
    }
}

// ---------------------------------------------------------------------------
// Launch. Inputs (metadata order): X, w_i,u_i,b_i, w_f,u_f,b_f, w_c,u_c,b_c,
// w_o,u_o,b_o. Output: [hidden_seq (B,S,H) | h_T (B,H) | c_T (B,H)] fp32.
// ---------------------------------------------------------------------------
extern "C" void kernel_launch(void* const* d_in, const int* in_sizes, int n_in,
                              void* d_out, int out_size) {
    (void)in_sizes; (void)n_in; (void)out_size;
    const float* X   = (const float*)d_in[0];
    const float* w_i = (const float*)d_in[1];
    const float* u_i = (const float*)d_in[2];
    const float* b_i = (const float*)d_in[3];
    const float* w_f = (const float*)d_in[4];
    const float* u_f = (const float*)d_in[5];
    const float* b_f = (const float*)d_in[6];
    const float* w_c = (const float*)d_in[7];
    const float* u_c = (const float*)d_in[8];
    const float* b_c = (const float*)d_in[9];
    const float* w_o = (const float*)d_in[10];
    const float* u_o = (const float*)d_in[11];
    const float* b_o = (const float*)d_in[12];
    float* out = (float*)d_out;

    lstm_init<<<64, 256>>>();

    dim3 g1(32, 128);   // N/128 x M/128
    xg_gemm<<<g1, 256>>>(X, w_i, w_f, w_c, w_o, b_i, b_f, b_c, b_o);

    cudaFuncSetAttribute(lstm_rec, cudaFuncAttributeMaxDynamicSharedMemorySize,
                         SMEM_P2);
    lstm_rec<<<NB2, NT2, SMEM_P2>>>(u_i, u_f, u_c, u_o, out);
}

// round 9
// speedup vs baseline: 1.2672x; 1.1301x over previous
#include <cuda_runtime.h>
#include <cuda_bf16.h>
#include <cstdint>
#include <cstddef>

#define BATCH 32
#define SEQ   512
#define ISZ   512
#define HSZ   1024
#define G4    4096
#define NB2   128
#define NT2   256

typedef unsigned long long ull;

// ---------------------------------------------------------------------------
// Device scratch (allocation-free rule: __device__ globals).
// g_Xg : [s][b][4096] input projections + bias, fp32, 256MB.
// g_h  : ping-pong hidden state, natural [b][k] layout.
// g_Upk: k-pair-packed recurrent weights, [hb][cgrp][p][c4] ull, 16MB.
// ---------------------------------------------------------------------------
__device__ float    g_Xg[(size_t)SEQ * BATCH * G4];
__device__ float    g_h[2][BATCH * HSZ];
__device__ ull      g_Upk[(size_t)128 * 8 * 512 * 4];
__device__ unsigned g_cnt;

// ---------------------------------------------------------------------------
// f32x2 packed fp32 FMA (sm_100+): 2 MACs/instr.
// ---------------------------------------------------------------------------
__device__ __forceinline__ void fma2(ull& d, ull a, ull b) {
    asm("fma.rn.f32x2 %0, %1, %2, %0;" : "+l"(d) : "l"(a), "l"(b));
}
__device__ __forceinline__ ull pk2(float x, float y) {
    ull r; asm("mov.b64 %0, {%1, %2};" : "=l"(r) : "f"(x), "f"(y)); return r;
}
__device__ __forceinline__ float2 upk(ull v) {
    float2 r; asm("mov.b64 {%0, %1}, %2;" : "=f"(r.x), "=f"(r.y) : "l"(v)); return r;
}

// cp.async 16B, L1-bypass (.cg) — reads L2 directly (coherent with stcg writes).
__device__ __forceinline__ void cpa16(uint32_t saddr, const void* gptr) {
    asm volatile("cp.async.cg.shared.global [%0], [%1], 16;"
                 :: "r"(saddr), "l"(gptr) : "memory");
}
__device__ __forceinline__ void cpa_commit() {
    asm volatile("cp.async.commit_group;" ::: "memory");
}
__device__ __forceinline__ void cpa_wait1() {
    asm volatile("cp.async.wait_group 1;" ::: "memory");
}

// ---------------------------------------------------------------------------
// Init: zero h0 and barrier counter (runs every graph replay).
// ---------------------------------------------------------------------------
__global__ void lstm_init() {
    unsigned t = blockIdx.x * blockDim.x + threadIdx.x;
    if (t == 0) g_cnt = 0u;
    unsigned stride = gridDim.x * blockDim.x;
    for (unsigned i = t; i < BATCH * HSZ; i += stride) {
        g_h[0][i] = 0.f;
        g_h[1][i] = 0.f;
    }
}

// ---------------------------------------------------------------------------
// Pack U into k-pair layout: g_Upk[((hb*8+cg)*512 + p)*4 + c] =
//   { u_gate[2p][col], u_gate[2p+1][col] },  col = hb*8 + (cg&1)*4 + c.
// One-time per replay (~30us).
// ---------------------------------------------------------------------------
__global__ __launch_bounds__(256)
void pack_u(const float* __restrict__ u0, const float* __restrict__ u1,
            const float* __restrict__ u2, const float* __restrict__ u3)
{
    unsigned idx = blockIdx.x * 256u + threadIdx.x;     // 0 .. 2^21-1
    int c  = idx & 3;
    int p  = (idx >> 2) & 511;
    int cg = (idx >> 11) & 7;
    int hb = (idx >> 14) & 127;
    int gate = cg >> 1;
    int col  = hb * 8 + (cg & 1) * 4 + c;
    const float* u = (gate == 0) ? u0 : (gate == 1) ? u1 : (gate == 2) ? u2 : u3;
    g_Upk[idx] = pk2(u[(size_t)(2 * p) * HSZ + col],
                     u[(size_t)(2 * p + 1) * HSZ + col]);
}

// ---------------------------------------------------------------------------
// Phase 1: Xg = X @ [Wi|Wf|Wc|Wo] + b  (known-good from R5; unchanged).
// ---------------------------------------------------------------------------
__global__ __launch_bounds__(256, 2)
void xg_gemm(const float* __restrict__ X,
             const float* __restrict__ w0, const float* __restrict__ w1,
             const float* __restrict__ w2, const float* __restrict__ w3,
             const float* __restrict__ bi0, const float* __restrict__ bi1,
             const float* __restrict__ bi2, const float* __restrict__ bi3)
{
    __shared__ float2 As2[16 * 128];
    __shared__ float  Bs [16 * 128];

    const int tid  = threadIdx.x;
    const int n0   = blockIdx.x * 128;
    const int m0   = blockIdx.y * 128;
    const int gate = blockIdx.x >> 3;
    const float* W  = (gate == 0) ? w0 : (gate == 1) ? w1 : (gate == 2) ? w2 : w3;
    const float* Bv = (gate == 0) ? bi0 : (gate == 1) ? bi1 : (gate == 2) ? bi2 : bi3;
    const int nloc = n0 & 1023;

    const int ar  = tid & 127;
    const int as4 = tid >> 7;
    const int mg  = m0 + ar;
    const float* Xrow = X + ((size_t)(mg & 31) * SEQ + (size_t)(mg >> 5)) * ISZ;

    const int bn4 = (tid & 31) * 4;
    const int bkr = tid >> 5;
    const int tx = tid & 15, ty = tid >> 4;

    ull acc[8][4];
    #pragma unroll
    for (int i = 0; i < 8; ++i)
        #pragma unroll
        for (int j = 0; j < 4; ++j) acc[i][j] = 0ULL;

    for (int kt = 0; kt < ISZ; kt += 16) {
        float4 a0 = *(const float4*)(Xrow + kt + as4 * 4);
        float4 a1 = *(const float4*)(Xrow + kt + (as4 + 2) * 4);
        float4 b0 = *(const float4*)(W + (size_t)(kt + bkr)     * HSZ + nloc + bn4);
        float4 b1 = *(const float4*)(W + (size_t)(kt + bkr + 8) * HSZ + nloc + bn4);

        __syncthreads();
        As2[(as4 * 4 + 0) * 128 + ar] = make_float2(a0.x, a0.x);
        As2[(as4 * 4 + 1) * 128 + ar] = make_float2(a0.y, a0.y);
        As2[(as4 * 4 + 2) * 128 + ar] = make_float2(a0.z, a0.z);
        As2[(as4 * 4 + 3) * 128 + ar] = make_float2(a0.w, a0.w);
        As2[((as4 + 2) * 4 + 0) * 128 + ar] = make_float2(a1.x, a1.x);
        As2[((as4 + 2) * 4 + 1) * 128 + ar] = make_float2(a1.y, a1.y);
        As2[((as4 + 2) * 4 + 2) * 128 + ar] = make_float2(a1.z, a1.z);
        As2[((as4 + 2) * 4 + 3) * 128 + ar] = make_float2(a1.w, a1.w);
        *(float4*)(Bs + bkr * 128 + bn4)       = b0;
        *(float4*)(Bs + (bkr + 8) * 128 + bn4) = b1;
        __syncthreads();

        #pragma unroll
        for (int k = 0; k < 16; ++k) {
            ull a[8], bb[4];
            ulonglong2 p;
            p = *(const ulonglong2*)(As2 + k * 128 + ty * 8);     a[0] = p.x; a[1] = p.y;
            p = *(const ulonglong2*)(As2 + k * 128 + ty * 8 + 2); a[2] = p.x; a[3] = p.y;
            p = *(const ulonglong2*)(As2 + k * 128 + ty * 8 + 4); a[4] = p.x; a[5] = p.y;
            p = *(const ulonglong2*)(As2 + k * 128 + ty * 8 + 6); a[6] = p.x; a[7] = p.y;
            p = *(const ulonglong2*)(Bs + k * 128 + tx * 8);      bb[0] = p.x; bb[1] = p.y;
            p = *(const ulonglong2*)(Bs + k * 128 + tx * 8 + 4);  bb[2] = p.x; bb[3] = p.y;
            #pragma unroll
            for (int i = 0; i < 8; ++i)
                #pragma unroll
                for (int j = 0; j < 4; ++j) fma2(acc[i][j], a[i], bb[j]);
        }
    }

    float4 bb0 = *(const float4*)(Bv + nloc + tx * 8);
    float4 bb1 = *(const float4*)(Bv + nloc + tx * 8 + 4);
    #pragma unroll
    for (int i = 0; i < 8; ++i) {
        float2 c0 = upk(acc[i][0]), c1 = upk(acc[i][1]);
        float2 c2 = upk(acc[i][2]), c3 = upk(acc[i][3]);
        float4 o0 = make_float4(c0.x + bb0.x, c0.y + bb0.y, c1.x + bb0.z, c1.y + bb0.w);
        float4 o1 = make_float4(c2.x + bb1.x, c2.y + bb1.y, c3.x + bb1.z, c3.y + bb1.w);
        size_t row = (size_t)(m0 + ty * 8 + i) * G4 + n0 + tx * 8;
        *(float4*)(g_Xg + row)     = o0;
        *(float4*)(g_Xg + row + 4) = o1;
    }
}

// ---------------------------------------------------------------------------
// Phase 2: persistent recurrence, k-paired f32x2 edition.
// Block hb: 8 hidden units x 4 gates x 32 batches (32 cols, K=1024).
// Thread (og, ks): og -> 4 batches (bg) x 4 cols (cgrp); ks -> 256-k split.
// h in smem [b][k], XOR-swizzled by (k-granule ^ b>>2) -> conflict-free LDS.
// U prefetched from g_Upk, distance-2, triple register buffers A/B/C.
// Per-ks cp.async staging + named barriers; Xg double-buffered 1 step ahead.
// smem: Hs 128KB + Rs 16KB + Gs 4KB + XgS 8KB = 156KB -> 1 block/SM.
// ---------------------------------------------------------------------------
#define SMEM_P2 ((32768 + 4096 + 1024 + 2048) * 4)

// prefetch group pg (16 ull = 128B contiguous) into register buffer
#define PF(BUF, pg) do {                                                       \
    const ulonglong2* _s = (const ulonglong2*)(ustream + (size_t)(pg) * 16);   \
    BUF[0] = _s[0]; BUF[1] = _s[1]; BUF[2] = _s[2]; BUF[3] = _s[3];            \
    BUF[4] = _s[4]; BUF[5] = _s[5]; BUF[6] = _s[6]; BUF[7] = _s[7];            \
} while (0)

// one granule (4 k = 2 pairs) for 4 batches against U pairs (q0,q0+1)
#define SUB(BUF, gran, q0) do {                                                \
    const int _go = (((gran)) ^ bg) << 2;                                      \
    ulonglong2 h0 = *(const ulonglong2*)(hTb + _go);                           \
    ulonglong2 h1 = *(const ulonglong2*)(hTb + 1024 + _go);                    \
    ulonglong2 h2 = *(const ulonglong2*)(hTb + 2048 + _go);                    \
    ulonglong2 h3 = *(const ulonglong2*)(hTb + 3072 + _go);                    \
    fma2(a00, h0.x, BUF[(q0)*2+0].x); fma2(a01, h0.x, BUF[(q0)*2+0].y);        \
    fma2(a02, h0.x, BUF[(q0)*2+1].x); fma2(a03, h0.x, BUF[(q0)*2+1].y);        \
    fma2(a10, h1.x, BUF[(q0)*2+0].x); fma2(a11, h1.x, BUF[(q0)*2+0].y);        \
    fma2(a12, h1.x, BUF[(q0)*2+1].x); fma2(a13, h1.x, BUF[(q0)*2+1].y);        \
    fma2(a20, h2.x, BUF[(q0)*2+0].x); fma2(a21, h2.x, BUF[(q0)*2+0].y);        \
    fma2(a22, h2.x, BUF[(q0)*2+1].x); fma2(a23, h2.x, BUF[(q0)*2+1].y);        \
    fma2(a30, h3.x, BUF[(q0)*2+0].x); fma2(a31, h3.x, BUF[(q0)*2+0].y);        \
    fma2(a32, h3.x, BUF[(q0)*2+1].x); fma2(a33, h3.x, BUF[(q0)*2+1].y);        \
    fma2(a00, h0.y, BUF[(q0)*2+2].x); fma2(a01, h0.y, BUF[(q0)*2+2].y);        \
    fma2(a02, h0.y, BUF[(q0)*2+3].x); fma2(a03, h0.y, BUF[(q0)*2+3].y);        \
    fma2(a10, h1.y, BUF[(q0)*2+2].x); fma2(a11, h1.y, BUF[(q0)*2+2].y);        \
    fma2(a12, h1.y, BUF[(q0)*2+3].x); fma2(a13, h1.y, BUF[(q0)*2+3].y);        \
    fma2(a20, h2.y, BUF[(q0)*2+2].x); fma2(a21, h2.y, BUF[(q0)*2+2].y);        \
    fma2(a22, h2.y, BUF[(q0)*2+3].x); fma2(a23, h2.y, BUF[(q0)*2+3].y);        \
    fma2(a30, h3.y, BUF[(q0)*2+2].x); fma2(a31, h3.y, BUF[(q0)*2+2].y);        \
    fma2(a32, h3.y, BUF[(q0)*2+3].x); fma2(a33, h3.y, BUF[(q0)*2+3].y);        \
} while (0)

// one group g: granules (ks*64 + g*2, +1), U pairs 0..3 of BUF
#define GRP(BUF, g) do {                                                       \
    SUB(BUF, ks * 64 + (g) * 2,     0);                                        \
    SUB(BUF, ks * 64 + (g) * 2 + 1, 2);                                        \
} while (0)

__global__ __launch_bounds__(NT2, 1)
void lstm_rec(float* __restrict__ out)
{
    extern __shared__ float sm[];
    float* Hs  = sm;                         // [b][k] swizzled, 128KB
    float* Rs  = sm + 32768;                 // [ks][1024] split-K partials
    float* Gs  = sm + 32768 + 4096;          // [b][32] gate pre-activations
    float* XgS = sm + 32768 + 4096 + 1024;   // 2 x [b][32] Xg slices

    const int tid = threadIdx.x;
    const int hb  = blockIdx.x;

    // compute role
    const int og   = tid & 63;
    const int ks   = tid >> 6;
    const int bg   = og & 7;
    const int cgrp = og >> 3;
    const ull* ustream = g_Upk + ((size_t)(hb * 8 + cgrp) * 512 + ks * 128) * 4;
    const float* hTb_base;  // set after Hs known
    const float* hTb = Hs + bg * 4 * 1024;
    (void)hTb_base;

    // staging role (warp-pair ksw stages its own k-range)
    const int wA  = tid >> 5;
    const int ksw = wA >> 1;
    const int t64 = (wA & 1) * 32 + (tid & 31);

    // epilogue role
    const int ub = tid >> 3;
    const int j  = tid & 7;
    const int kglob = hb * 8 + j;
    float creg = 0.f;

    // Xg staging role: one 16B chunk: batch xb, 4-col group xq
    const int xb = tid >> 3, xq = tid & 7;
    const size_t xgcol = (size_t)(xq >> 1) * 1024 + hb * 8 + (xq & 1) * 4;

    const uint32_t HsA = (uint32_t)__cvta_generic_to_shared(Hs);
    const uint32_t XgA = (uint32_t)__cvta_generic_to_shared(XgS);

    float* out_h = out + (size_t)BATCH * SEQ * HSZ;
    float* out_c = out_h + BATCH * HSZ;

    ulonglong2 A[8], B[8], C[8];

    // prologue: Xg slice for step 0 into buffer 0; U groups 0,1
    cpa16(XgA + (uint32_t)(xb * 32 + xq * 4) * 4u,
          g_Xg + (size_t)xb * G4 + xgcol);
    cpa_commit();                       // pending: X_0
    PF(A, 0); PF(B, 1);

    int cur = 0;
    for (int s = 0; s < SEQ; ++s) {
        // --- stage this warp-pair's h k-range (32KB) via cp.async ---
        {
            const float* hsrc = g_h[cur];
            #pragma unroll
            for (int i = 0; i < 32; ++i) {
                int gsrc = ksw * 64 + t64;                 // k-granule
                int sw   = gsrc ^ (i >> 2);                // swizzle by b>>2
                cpa16(HsA + (uint32_t)(i * 1024 + sw * 4) * 4u,
                      hsrc + i * 1024 + gsrc * 4);
            }
            cpa_commit();                                  // H_s
        }
        // --- prefetch Xg for step s+1 (other buffer) ---
        {
            int sn = (s + 1 < SEQ) ? s + 1 : SEQ - 1;
            cpa16(XgA + (uint32_t)(((s + 1) & 1) * 1024 + xb * 32 + xq * 4) * 4u,
                  g_Xg + ((size_t)sn * BATCH + xb) * G4 + xgcol);
            cpa_commit();                                  // X_{s+1}
        }
        cpa_wait1();    // waits X_s + H_s complete; X_{s+1} stays in flight
        asm volatile("bar.sync %0, 64;" :: "r"(1 + ksw) : "memory");

        // --- split-K GEMM, k-paired, distance-2 triple-buffered U ---
        ull a00 = 0, a01 = 0, a02 = 0, a03 = 0;
        ull a10 = 0, a11 = 0, a12 = 0, a13 = 0;
        ull a20 = 0, a21 = 0, a22 = 0, a23 = 0;
        ull a30 = 0, a31 = 0, a32 = 0, a33 = 0;
        #pragma unroll
        for (int t = 0; t < 10; ++t) {
            GRP(A, t * 3 + 0); PF(C, t * 3 + 2);
            GRP(B, t * 3 + 1); PF(A, t * 3 + 3);
            GRP(C, t * 3 + 2); PF(B, t * 3 + 4);
        }
        GRP(A, 30); PF(A, 0);            // refill for next step (U invariant)
        GRP(B, 31); PF(B, 1);

        // --- write split-K partials (sum pair halves) ---
        {
            float* r = Rs + ks * 1024 + og * 16;
            float2 t;
            t = upk(a00); r[0]  = t.x + t.y;  t = upk(a01); r[1]  = t.x + t.y;
            t = upk(a02); r[2]  = t.x + t.y;  t = upk(a03); r[3]  = t.x + t.y;
            t = upk(a10); r[4]  = t.x + t.y;  t = upk(a11); r[5]  = t.x + t.y;
            t = upk(a12); r[6]  = t.x + t.y;  t = upk(a13); r[7]  = t.x + t.y;
            t = upk(a20); r[8]  = t.x + t.y;  t = upk(a21); r[9]  = t.x + t.y;
            t = upk(a22); r[10] = t.x + t.y;  t = upk(a23); r[11] = t.x + t.y;
            t = upk(a30); r[12] = t.x + t.y;  t = upk(a31); r[13] = t.x + t.y;
            t = upk(a32); r[14] = t.x + t.y;  t = upk(a33); r[15] = t.x + t.y;
        }
        __syncthreads();

        // --- reduce 4 partials + add Xg (smem) -> Gs[b][c] ---
        const float* Xcur = XgS + (s & 1) * 1024;
        #pragma unroll
        for (int i = 0; i < 4; ++i) {
            int o   = tid * 4 + i;
            int oog = o >> 4, li = o & 15;
            int bb  = (oog & 7) * 4 + (li >> 2);
            int cc  = (oog >> 3) * 4 + (li & 3);
            float v = Rs[o] + Rs[1024 + o] + Rs[2048 + o] + Rs[3072 + o];
            v += Xcur[bb * 32 + cc];
            Gs[bb * 32 + cc] = v;
        }
        __syncthreads();

        // --- gates + state update (role: ub, j) ---
        {
            float gi = Gs[ub * 32 + j];
            float gf = Gs[ub * 32 + 8 + j];
            float gc = Gs[ub * 32 + 16 + j];
            float go = Gs[ub * 32 + 24 + j];
            float it = 1.f / (1.f + __expf(-gi));
            float ft = 1.f / (1.f + __expf(-gf));
            float ct = tanhf(gc);
            float ot = 1.f / (1.f + __expf(-go));
            creg = ft * creg + it * ct;
            float hn = ot * tanhf(creg);
            __stcg(&g_h[cur ^ 1][ub * HSZ + kglob], hn);
            out[((size_t)ub * SEQ + s) * HSZ + kglob] = hn;
            if (s == SEQ - 1) {
                out_h[ub * HSZ + kglob] = hn;
                out_c[ub * HSZ + kglob] = creg;
            }
        }

        // --- grid barrier: release-add + acquire-spin (grid.sync pattern) ---
        __syncthreads();
        if (tid == 0) {
            unsigned old;
            asm volatile("atom.add.release.gpu.u32 %0, [%1], 1;"
                         : "=r"(old) : "l"(&g_cnt) : "memory");
            unsigned target = (unsigned)NB2 * (unsigned)(s + 1);
            unsigned v;
            do {
                asm volatile("ld.acquire.gpu.u32 %0, [%1];"
                             : "=r"(v) : "l"(&g_cnt) : "memory");
            } while (v < target);
        }
        __syncthreads();
        cur ^= 1;
    }
}

// ---------------------------------------------------------------------------
// Launch. Inputs: X, w_i,u_i,b_i, w_f,u_f,b_f, w_c,u_c,b_c, w_o,u_o,b_o.
// Output: [hidden_seq (B,S,H) | h_T (B,H) | c_T (B,H)] fp32.
// ---------------------------------------------------------------------------
extern "C" void kernel_launch(void* const* d_in, const int* in_sizes, int n_in,
                              void* d_out, int out_size) {
    (void)in_sizes; (void)n_in; (void)out_size;
    const float* X   = (const float*)d_in[0];
    const float* w_i = (const float*)d_in[1];
    const float* u_i = (const float*)d_in[2];
    const float* b_i = (const float*)d_in[3];
    const float* w_f = (const float*)d_in[4];
    const float* u_f = (const float*)d_in[5];
    const float* b_f = (const float*)d_in[6];
    const float* w_c = (const float*)d_in[7];
    const float* u_c = (const float*)d_in[8];
    const float* b_c = (const float*)d_in[9];
    const float* w_o = (const float*)d_in[10];
    const float* u_o = (const float*)d_in[11];
    const float* b_o = (const float*)d_in[12];
    float* out = (float*)d_out;

    lstm_init<<<64, 256>>>();
    pack_u<<<8192, 256>>>(u_i, u_f, u_c, u_o);

    dim3 g1(32, 128);   // N/128 x M/128
    xg_gemm<<<g1, 256>>>(X, w_i, w_f, w_c, w_o, b_i, b_f, b_c, b_o);

    cudaFuncSetAttribute(lstm_rec, cudaFuncAttributeMaxDynamicSharedMemorySize,
                         SMEM_P2);
    lstm_rec<<<NB2, NT2, SMEM_P2>>>(out);
}